// round 14
// baseline (speedup 1.0000x reference)
#include <cuda_runtime.h>
#include <cuda_bf16.h>
#include <cstdint>

#define V 32768
#define KTOT 131584
#define NB 4
#define NF 128
#define FIN 384

#define OFF_WIN  0
#define OFF_BIN  49152
#define OFF_WMID 49280
#define OFF_BMID 65664
#define OFF_WOUT 65792
#define OFF_BOUT 82176
#define OFF_WSH  82304
#define OFF_BSH  131456

__device__ float g_ks[NB * KTOT];
__device__ float g_out[NB * NF * V];
__device__ __nv_bfloat16 g_yhi[NB * FIN * V];
__device__ __nv_bfloat16 g_ylo[NB * FIN * V];
__device__ __nv_bfloat16 g_A0hi[NB * 256 * FIN];
__device__ __nv_bfloat16 g_A0lo[NB * 256 * FIN];
__device__ __nv_bfloat16 g_A12hi[NB * 2 * NF * NF];
__device__ __nv_bfloat16 g_A12lo[NB * 2 * NF * NF];
__device__ float g_bias0[NB * 256];
__device__ float g_bias12[NB * 2 * NF];
__device__ float g_pstat[NB * FIN * 4];

// ===================== helpers =====================
__device__ __forceinline__ uint32_t smem_u32(const void* p) {
    uint32_t a;
    asm("{ .reg .u64 t; cvta.to.shared.u64 t, %1; cvt.u32.u64 %0, t; }"
        : "=r"(a) : "l"(p));
    return a;
}
__device__ __forceinline__ uint32_t pack_split(float v) {
    __nv_bfloat16 h = __float2bfloat16_rn(v);
    __nv_bfloat16 l = __float2bfloat16_rn(v - __bfloat162float(h));
    return (uint32_t)__bfloat16_as_ushort(h) |
           ((uint32_t)__bfloat16_as_ushort(l) << 16);
}
__device__ __forceinline__ void split2(float a, float b, uint32_t& hp, uint32_t& lp) {
    uint32_t pa = pack_split(a), pb = pack_split(b);
    hp = __byte_perm(pa, pb, 0x5410);
    lp = __byte_perm(pa, pb, 0x7632);
}
__device__ __forceinline__ void tsplit(float v, __nv_bfloat16& h, __nv_bfloat16& l) {
    uint32_t u = __float_as_uint(v);
    h = __ushort_as_bfloat16((unsigned short)(u >> 16));
    l = __float2bfloat16_rn(v - __uint_as_float(u & 0xFFFF0000u));
}
__device__ __forceinline__ void ldsm4(uint32_t* r, uint32_t a) {
    asm volatile("ldmatrix.sync.aligned.m8n8.x4.shared.b16 {%0,%1,%2,%3}, [%4];"
                 : "=r"(r[0]), "=r"(r[1]), "=r"(r[2]), "=r"(r[3]) : "r"(a));
}
__device__ __forceinline__ void ldsm4t(uint32_t* r, uint32_t a) {
    asm volatile("ldmatrix.sync.aligned.m8n8.x4.trans.shared.b16 {%0,%1,%2,%3}, [%4];"
                 : "=r"(r[0]), "=r"(r[1]), "=r"(r[2]), "=r"(r[3]) : "r"(a));
}
__device__ __forceinline__ void mma_bf16(float* c, const uint32_t* a,
                                         const uint32_t* bb) {
    asm volatile(
        "mma.sync.aligned.m16n8k16.row.col.f32.bf16.bf16.f32 "
        "{%0,%1,%2,%3}, {%4,%5,%6,%7}, {%8,%9}, {%0,%1,%2,%3};"
        : "+f"(c[0]), "+f"(c[1]), "+f"(c[2]), "+f"(c[3])
        : "r"(a[0]), "r"(a[1]), "r"(a[2]), "r"(a[3]), "r"(bb[0]), "r"(bb[1]));
}
__device__ __forceinline__ void cpa16(uint32_t dst, const void* src) {
    asm volatile("cp.async.cg.shared.global [%0], [%1], 16;" :: "r"(dst), "l"(src));
}
#define CPA_COMMIT() asm volatile("cp.async.commit_group;" ::: "memory")
#define CPA_WAIT0()  asm volatile("cp.async.wait_group 0;" ::: "memory")
#define SWZ(o)   ((o) ^ (((o) >> 3) & 0x70))
#define SWZ64(o) ((o) ^ (((o) >> 3) & 0x30))

// ===================== hypernet =====================
__global__ void __launch_bounds__(256) hyper_kernel(
    const float* __restrict__ lat, const float* __restrict__ Wk,
    const float* __restrict__ bk)
{
    __shared__ float slat[4 * 512];
    for (int i = threadIdx.x; i < 2048; i += 256) slat[i] = lat[i];
    __syncthreads();
    int j = blockIdx.x * 256 + threadIdx.x;
    if (j >= KTOT) return;
    float bv = bk[j];
    float a0 = bv, a1 = bv, a2 = bv, a3 = bv;
    const float* wp = Wk + j;
#pragma unroll 8
    for (int k = 0; k < 512; k++) {
        float w = wp[(size_t)k * KTOT];
        a0 = fmaf(slat[k], w, a0);
        a1 = fmaf(slat[512 + k], w, a1);
        a2 = fmaf(slat[1024 + k], w, a2);
        a3 = fmaf(slat[1536 + k], w, a3);
    }
    g_ks[j] = a0;
    g_ks[KTOT + j] = a1;
    g_ks[2 * KTOT + j] = a2;
    g_ks[3 * KTOT + j] = a3;
}

// ===================== seed instance-norm =====================
__global__ void __launch_bounds__(256) seed_norm_kernel(const float* __restrict__ seed)
{
    int c = blockIdx.x;
    const float* src = seed + (size_t)c * V;
    float s = 0.f, ss = 0.f;
    for (int i = threadIdx.x; i < V; i += 256) {
        float v = src[i];
        s += v;
        ss = fmaf(v, v, ss);
    }
#pragma unroll
    for (int o = 16; o > 0; o >>= 1) {
        s += __shfl_down_sync(0xffffffffu, s, o);
        ss += __shfl_down_sync(0xffffffffu, ss, o);
    }
    __shared__ float red[2][8];
    __shared__ float st[2];
    int warp = threadIdx.x >> 5, lane = threadIdx.x & 31;
    if (lane == 0) { red[0][warp] = s; red[1][warp] = ss; }
    __syncthreads();
    if (threadIdx.x == 0) {
        float S = 0.f, SS = 0.f;
        for (int w = 0; w < 8; w++) { S += red[0][w]; SS += red[1][w]; }
        float mean = S * (1.0f / V);
        float var = SS * (1.0f / V) - mean * mean;
        st[0] = mean;
        st[1] = rsqrtf(var + 1e-5f);
    }
    __syncthreads();
    float mean = st[0], rstd = st[1];
    for (int i = threadIdx.x; i < V; i += 256) {
        float v = (src[i] - mean) * rstd;
        size_t off = ((size_t)c << 15) + i;
        g_out[off] = v;
        g_out[off + ((size_t)128 << 15)] = v;
        g_out[off + ((size_t)256 << 15)] = v;
        g_out[off + ((size_t)384 << 15)] = v;
    }
}

// ===================== sobel conv + partial stats (writes y planes) ==========
__global__ void __launch_bounds__(512) conv_kernel()
{
    extern __shared__ float sx[];
    int bc2 = blockIdx.x;
    int half = bc2 & 1, bc = bc2 >> 1;
    int b = bc >> 7, c = bc & 127;
    int d0 = half * 16;
    const float* src = g_out + ((size_t)bc << 15);

    for (int i = threadIdx.x; i < 18 * 256; i += 512) {
        int si = i >> 8;
        int gd = d0 - 1 + si;
        float4 v = make_float4(0.f, 0.f, 0.f, 0.f);
        if ((unsigned)gd < 32u) v = ((const float4*)(src + gd * 1024))[i & 255];
        ((float4*)sx)[i] = v;
    }
    __syncthreads();

    int warp = threadIdx.x >> 5, lane = threadIdx.x & 31;
    size_t fbase = ((size_t)(b * FIN + 3 * c)) << 15;
    __nv_bfloat16* yh = g_yhi + fbase;
    __nv_bfloat16* yl = g_ylo + fbase;

    float s0s = 0.f, s0q = 0.f, s1s = 0.f, s1q = 0.f, s2s = 0.f, s2q = 0.f;

    for (int row = warp; row < 512; row += 16) {
        int ld = row >> 5, h = row & 31;
        float cv[3][3];
#pragma unroll
        for (int i = 0; i < 3; i++) {
#pragma unroll
            for (int j = 0; j < 3; j++) {
                int hh = h + j - 1;
                cv[i][j] = ((unsigned)hh < 32u)
                               ? sx[(ld + i) * 1024 + hh * 32 + lane]
                               : 0.f;
            }
        }
        float S0 = (cv[2][0] + cv[2][1] + cv[2][2]) - (cv[0][0] + cv[0][1] + cv[0][2]);
        float S1 = (cv[0][2] + cv[1][2] + cv[2][2]) - (cv[0][0] + cv[1][0] + cv[2][0]);
        float S2 = cv[0][0] + cv[0][1] + cv[0][2] + cv[1][0] + cv[1][1] + cv[1][2] +
                   cv[2][0] + cv[2][1] + cv[2][2];
        float l0 = __shfl_up_sync(0xffffffffu, S0, 1);   if (lane == 0)  l0 = 0.f;
        float r0 = __shfl_down_sync(0xffffffffu, S0, 1); if (lane == 31) r0 = 0.f;
        float l1 = __shfl_up_sync(0xffffffffu, S1, 1);   if (lane == 0)  l1 = 0.f;
        float r1 = __shfl_down_sync(0xffffffffu, S1, 1); if (lane == 31) r1 = 0.f;
        float l2 = __shfl_up_sync(0xffffffffu, S2, 1);   if (lane == 0)  l2 = 0.f;
        float r2 = __shfl_down_sync(0xffffffffu, S2, 1); if (lane == 31) r2 = 0.f;
        float y0 = S0 + l0 + r0;
        float y1 = S1 + l1 + r1;
        float y2 = r2 - l2;
        int voxel = ((d0 + ld) << 10) + (h << 5) + lane;
        __nv_bfloat16 hh0, ll0, hh1, ll1, hh2, ll2;
        tsplit(y0, hh0, ll0);
        tsplit(y1, hh1, ll1);
        tsplit(y2, hh2, ll2);
        yh[voxel] = hh0;          yl[voxel] = ll0;
        yh[V + voxel] = hh1;      yl[V + voxel] = ll1;
        yh[2 * V + voxel] = hh2;  yl[2 * V + voxel] = ll2;
        s0s += y0; s0q = fmaf(y0, y0, s0q);
        s1s += y1; s1q = fmaf(y1, y1, s1q);
        s2s += y2; s2q = fmaf(y2, y2, s2q);
    }

#pragma unroll
    for (int o = 16; o > 0; o >>= 1) {
        s0s += __shfl_down_sync(0xffffffffu, s0s, o);
        s0q += __shfl_down_sync(0xffffffffu, s0q, o);
        s1s += __shfl_down_sync(0xffffffffu, s1s, o);
        s1q += __shfl_down_sync(0xffffffffu, s1q, o);
        s2s += __shfl_down_sync(0xffffffffu, s2s, o);
        s2q += __shfl_down_sync(0xffffffffu, s2q, o);
    }
    __shared__ float rbuf[16][6];
    if (lane == 0) {
        rbuf[warp][0] = s0s; rbuf[warp][1] = s0q;
        rbuf[warp][2] = s1s; rbuf[warp][3] = s1q;
        rbuf[warp][4] = s2s; rbuf[warp][5] = s2q;
    }
    __syncthreads();
    if (threadIdx.x < 3) {
        int a = threadIdx.x;
        float S = 0.f, SQ = 0.f;
        for (int w = 0; w < 16; w++) { S += rbuf[w][2 * a]; SQ += rbuf[w][2 * a + 1]; }
        int f = b * FIN + 3 * c + a;
        g_pstat[f * 4 + half * 2 + 0] = S;
        g_pstat[f * 4 + half * 2 + 1] = SQ;
    }
}

// ===================== weight prep =====================
__global__ void __launch_bounds__(128) prep_A0_kernel()
{
    int ms = blockIdx.x;
    int b = blockIdx.y;
    const float* ksb = g_ks + (size_t)b * KTOT;
    const float* w = (ms < 128) ? ksb + OFF_WIN + (size_t)ms * FIN
                                : ksb + OFF_WSH + (size_t)(ms - 128) * FIN;
    float b0 = (ms < 128) ? ksb[OFF_BIN + ms] : ksb[OFF_BSH + ms - 128];
    const float* pst = g_pstat + (size_t)(b * FIN) * 4;
    __nv_bfloat16* dh = g_A0hi + ((size_t)b * 256 + ms) * FIN;
    __nv_bfloat16* dl = g_A0lo + ((size_t)b * 256 + ms) * FIN;
    float dot = 0.f;
    for (int k = threadIdx.x; k < FIN; k += 128) {
        float sum = pst[k * 4 + 0] + pst[k * 4 + 2];
        float sq = pst[k * 4 + 1] + pst[k * 4 + 3];
        float mn = sum * (1.0f / V);
        float rs = rsqrtf(sq * (1.0f / V) - mn * mn + 1e-5f);
        float a = w[k] * rs;
        __nv_bfloat16 h = __float2bfloat16_rn(a);
        dh[k] = h;
        dl[k] = __float2bfloat16_rn(a - __bfloat162float(h));
        dot = fmaf(a, mn, dot);
    }
#pragma unroll
    for (int o = 16; o > 0; o >>= 1) dot += __shfl_down_sync(0xffffffffu, dot, o);
    __shared__ float rr[4];
    int warp = threadIdx.x >> 5;
    if ((threadIdx.x & 31) == 0) rr[warp] = dot;
    __syncthreads();
    if (threadIdx.x == 0)
        g_bias0[b * 256 + ms] = b0 - (rr[0] + rr[1] + rr[2] + rr[3]);
}

__global__ void __launch_bounds__(128) prep_A12_kernel()
{
    int m = blockIdx.x;
    int b = blockIdx.y;
    const float* ksb = g_ks + (size_t)b * KTOT;
    int k = threadIdx.x;
    float wm = ksb[OFF_WMID + m * 128 + k];
    float wo = ksb[OFF_WOUT + m * 128 + k];
    __nv_bfloat16 hm = __float2bfloat16_rn(wm);
    __nv_bfloat16 ho = __float2bfloat16_rn(wo);
    size_t i0 = ((size_t)b * 2) * 16384 + m * 128 + k;
    size_t i1 = ((size_t)b * 2 + 1) * 16384 + m * 128 + k;
    g_A12hi[i0] = hm;
    g_A12lo[i0] = __float2bfloat16_rn(wm - __bfloat162float(hm));
    g_A12hi[i1] = ho;
    g_A12lo[i1] = __float2bfloat16_rn(wo - __bfloat162float(ho));
    if (k == 0) {
        g_bias12[b * 256 + m] = ksb[OFF_BMID + m];
        g_bias12[b * 256 + 128 + m] = ksb[OFF_BOUT + m];
    }
}

// ===================== fused residual block v6 (N=128, 512 thr, 1 CTA/SM) ===
// 16 warps: wm=wid&3 (row strips), wn=wid>>2 (col strips of 32; half=wn>>1).
// A0 chunk amortized over 128 voxels -> A0 L2 traffic halved vs N=64.
// smem (160KB): A0 bufs [0,32K)/[32K,64K); y bufs [64K,96K)
//   (buf c&1 at +16K, half at +8K; hi +0/lo +4K); A12 bufs [0,16K)/[16K,32K);
//   h2 halves [32K,96K) (per half: hi 16K + lo 16K); h1 halves [96K,160K).
__global__ void __launch_bounds__(512, 1) fused_gemm3_kernel()
{
    extern __shared__ char smem[];
    uint32_t sb = smem_u32(smem);
    int tid = threadIdx.x, lane = tid & 31, wid = tid >> 5;
    int wm = wid & 3, wn = wid >> 2;
    int half = wn >> 1, ncol = (wn & 1) * 32;
    int b = blockIdx.y;
    int n0 = blockIdx.x * 128;
    int lrow = lane & 15, lcol = (lane >> 4) * 8;
    int gid = lane >> 2, tig = lane & 3;

    const __nv_bfloat16* yh = g_yhi + ((size_t)b * FIN << 15);
    const __nv_bfloat16* yl = g_ylo + ((size_t)b * FIN << 15);
    const __nv_bfloat16* A0h = g_A0hi + (size_t)b * 256 * FIN;
    const __nv_bfloat16* A0l = g_A0lo + (size_t)b * 256 * FIN;
    const __nv_bfloat16* A12h = g_A12hi + (size_t)b * 2 * 16384;
    const __nv_bfloat16* A12l = g_A12lo + (size_t)b * 2 * 16384;

    int yhf = tid >> 8, yr = (tid >> 3) & 31, yseg = tid & 7;

    auto issueA0 = [&](int c) {
        uint32_t dh = sb + (c & 1) * 32768, dl = dh + 16384;
        const __nv_bfloat16* sh = A0h + c * 32;
        const __nv_bfloat16* sl = A0l + c * 32;
#pragma unroll
        for (int i = 0; i < 2; i++) {
            int q = tid + i * 512;
            int m = q >> 2, seg = q & 3;
            uint32_t off = SWZ64((uint32_t)(m * 64 + seg * 16));
            cpa16(dh + off, sh + (size_t)m * FIN + seg * 8);
            cpa16(dl + off, sl + (size_t)m * FIN + seg * 8);
        }
        uint32_t yb = sb + 65536 + (c & 1) * 16384 + yhf * 8192;
        uint32_t off = SWZ((uint32_t)(yr * 128 + yseg * 16));
        size_t gof = ((size_t)(c * 32 + yr) << 15) + n0 + yhf * 64 + yseg * 8;
        cpa16(yb + off, yh + gof);
        cpa16(yb + 4096 + off, yl + gof);
        CPA_COMMIT();
    };

    issueA0(0);

    float acc_h[2][4][4], acc_s[2][4][4];
#pragma unroll
    for (int mt = 0; mt < 2; mt++)
#pragma unroll
        for (int nt = 0; nt < 4; nt++)
#pragma unroll
            for (int q = 0; q < 4; q++) {
                acc_h[mt][nt][q] = 0.f;
                acc_s[mt][nt][q] = 0.f;
            }

    CPA_WAIT0();
    __syncthreads();

    // ---- stage A: 12 chunks of K=32 ----
    for (int c = 0; c < 12; c++) {
        if (c < 11) issueA0(c + 1);
        uint32_t ab = sb + (c & 1) * 32768;
        uint32_t ybh = sb + 65536 + (c & 1) * 16384 + half * 8192;
        uint32_t ybl = ybh + 4096;
#pragma unroll
        for (int ks = 0; ks < 2; ks++) {
            int kk = ks * 16;
            uint32_t bh[4][2], bl[4][2];
#pragma unroll
            for (int g = 0; g < 2; g++) {
                uint32_t off = SWZ(
                    (uint32_t)((kk + lrow) * 128 + (ncol + g * 16 + lcol) * 2));
                uint32_t t0[4], t1[4];
                ldsm4t(t0, ybh + off);
                ldsm4t(t1, ybl + off);
                bh[g * 2][0] = t0[0]; bh[g * 2][1] = t0[1];
                bh[g * 2 + 1][0] = t0[2]; bh[g * 2 + 1][1] = t0[3];
                bl[g * 2][0] = t1[0]; bl[g * 2][1] = t1[1];
                bl[g * 2 + 1][0] = t1[2]; bl[g * 2 + 1][1] = t1[3];
            }
            uint32_t ah[2][4], al[2][4];
#pragma unroll
            for (int mt = 0; mt < 2; mt++) {
                uint32_t off = SWZ64(
                    (uint32_t)((wm * 32 + mt * 16 + lrow) * 64 + (kk + lcol) * 2));
                ldsm4(ah[mt], ab + off);
                ldsm4(al[mt], ab + 16384 + off);
            }
#pragma unroll
            for (int mt = 0; mt < 2; mt++)
#pragma unroll
                for (int nt = 0; nt < 4; nt++) {
                    mma_bf16(acc_h[mt][nt], ah[mt], bh[nt]);
                    mma_bf16(acc_h[mt][nt], ah[mt], bl[nt]);
                    mma_bf16(acc_h[mt][nt], al[mt], bh[nt]);
                }
#pragma unroll
            for (int mt = 0; mt < 2; mt++) {
                uint32_t off = SWZ64((uint32_t)(
                    (128 + wm * 32 + mt * 16 + lrow) * 64 + (kk + lcol) * 2));
                ldsm4(ah[mt], ab + off);
                ldsm4(al[mt], ab + 16384 + off);
            }
#pragma unroll
            for (int mt = 0; mt < 2; mt++)
#pragma unroll
                for (int nt = 0; nt < 4; nt++) {
                    mma_bf16(acc_s[mt][nt], ah[mt], bh[nt]);
                    mma_bf16(acc_s[mt][nt], ah[mt], bl[nt]);
                    mma_bf16(acc_s[mt][nt], al[mt], bh[nt]);
                }
        }
        CPA_WAIT0();
        __syncthreads();
    }

    // issue stage-B chunk 0 -> [0,16K)
    {
        int q = tid, m = q >> 2, seg = q & 3;
        uint32_t off = SWZ64((uint32_t)(m * 64 + seg * 16));
        cpa16(sb + off, A12h + m * 128 + seg * 8);
        cpa16(sb + 8192 + off, A12l + m * 128 + seg * 8);
        CPA_COMMIT();
    }
    // stage-A h1 epilogue -> halves at [96K,160K)
    {
        uint32_t hbase = sb; (void)hbase;
#pragma unroll
        for (int mt = 0; mt < 2; mt++) {
            int r0 = wm * 32 + mt * 16 + gid, r1 = r0 + 8;
            float bi0 = g_bias0[b * 256 + r0], bi1 = g_bias0[b * 256 + r1];
#pragma unroll
            for (int nt = 0; nt < 4; nt++) {
                int n = ncol + nt * 8 + tig * 2;
                uint32_t hp, lp;
                split2(fmaxf(acc_h[mt][nt][0] + bi0, 0.f),
                       fmaxf(acc_h[mt][nt][1] + bi0, 0.f), hp, lp);
                uint32_t off = SWZ((uint32_t)(r0 * 128 + n * 2));
                *(uint32_t*)(smem + 98304 + half * 32768 + off) = hp;
                *(uint32_t*)(smem + 98304 + half * 32768 + 16384 + off) = lp;
                split2(fmaxf(acc_h[mt][nt][2] + bi1, 0.f),
                       fmaxf(acc_h[mt][nt][3] + bi1, 0.f), hp, lp);
                off = SWZ((uint32_t)(r1 * 128 + n * 2));
                *(uint32_t*)(smem + 98304 + half * 32768 + off) = hp;
                *(uint32_t*)(smem + 98304 + half * 32768 + 16384 + off) = lp;
            }
        }
    }
#pragma unroll
    for (int mt = 0; mt < 2; mt++)
#pragma unroll
        for (int nt = 0; nt < 4; nt++)
#pragma unroll
            for (int q = 0; q < 4; q++) acc_h[mt][nt][q] = 0.f;

    // ---- stages B & C: 8 chunk-rounds ----
    for (int idx = 0; idx < 8; idx++) {
        CPA_WAIT0();
        __syncthreads();
        if (idx < 7) {
            int ns = (idx + 1) >> 2, nc = (idx + 1) & 3;
            const __nv_bfloat16* sh = A12h + (size_t)ns * 16384 + nc * 32;
            const __nv_bfloat16* sl = A12l + (size_t)ns * 16384 + nc * 32;
            uint32_t dh = sb + ((idx + 1) & 1) * 16384, dl = dh + 8192;
            int q = tid, m = q >> 2, seg = q & 3;
            uint32_t off = SWZ64((uint32_t)(m * 64 + seg * 16));
            cpa16(dh + off, sh + m * 128 + seg * 8);
            cpa16(dl + off, sl + m * 128 + seg * 8);
            CPA_COMMIT();
        }
        uint32_t ab = sb + (idx & 1) * 16384;
        uint32_t srcH = sb + ((idx < 4) ? 98304 : 32768) + half * 32768;
        uint32_t srcL = srcH + 16384;
        int krow = (idx & 3) * 32;
#pragma unroll
        for (int ks = 0; ks < 2; ks++) {
            int kk = ks * 16;
            uint32_t bh[4][2], bl[4][2];
#pragma unroll
            for (int g = 0; g < 2; g++) {
                uint32_t off = SWZ((uint32_t)((krow + kk + lrow) * 128 +
                                              (ncol + g * 16 + lcol) * 2));
                uint32_t t0[4], t1[4];
                ldsm4t(t0, srcH + off);
                ldsm4t(t1, srcL + off);
                bh[g * 2][0] = t0[0]; bh[g * 2][1] = t0[1];
                bh[g * 2 + 1][0] = t0[2]; bh[g * 2 + 1][1] = t0[3];
                bl[g * 2][0] = t1[0]; bl[g * 2][1] = t1[1];
                bl[g * 2 + 1][0] = t1[2]; bl[g * 2 + 1][1] = t1[3];
            }
            uint32_t ah[2][4], al[2][4];
#pragma unroll
            for (int mt = 0; mt < 2; mt++) {
                uint32_t off = SWZ64(
                    (uint32_t)((wm * 32 + mt * 16 + lrow) * 64 + (kk + lcol) * 2));
                ldsm4(ah[mt], ab + off);
                ldsm4(al[mt], ab + 8192 + off);
            }
#pragma unroll
            for (int mt = 0; mt < 2; mt++)
#pragma unroll
                for (int nt = 0; nt < 4; nt++) {
                    mma_bf16(acc_h[mt][nt], ah[mt], bh[nt]);
                    mma_bf16(acc_h[mt][nt], ah[mt], bl[nt]);
                    mma_bf16(acc_h[mt][nt], al[mt], bh[nt]);
                }
        }
        if (idx == 3) {  // stage-B epilogue: h2 -> halves at [32K,96K)
#pragma unroll
            for (int mt = 0; mt < 2; mt++) {
                int r0 = wm * 32 + mt * 16 + gid, r1 = r0 + 8;
                float bi0 = g_bias12[b * 256 + r0], bi1 = g_bias12[b * 256 + r1];
#pragma unroll
                for (int nt = 0; nt < 4; nt++) {
                    int n = ncol + nt * 8 + tig * 2;
                    uint32_t hp, lp;
                    split2(fmaxf(acc_h[mt][nt][0] + bi0, 0.f),
                           fmaxf(acc_h[mt][nt][1] + bi0, 0.f), hp, lp);
                    uint32_t off = SWZ((uint32_t)(r0 * 128 + n * 2));
                    *(uint32_t*)(smem + 32768 + half * 32768 + off) = hp;
                    *(uint32_t*)(smem + 32768 + half * 32768 + 16384 + off) = lp;
                    split2(fmaxf(acc_h[mt][nt][2] + bi1, 0.f),
                           fmaxf(acc_h[mt][nt][3] + bi1, 0.f), hp, lp);
                    off = SWZ((uint32_t)(r1 * 128 + n * 2));
                    *(uint32_t*)(smem + 32768 + half * 32768 + off) = hp;
                    *(uint32_t*)(smem + 32768 + half * 32768 + 16384 + off) = lp;
                }
            }
#pragma unroll
            for (int mt = 0; mt < 2; mt++)
#pragma unroll
                for (int nt = 0; nt < 4; nt++)
#pragma unroll
                    for (int q = 0; q < 4; q++) acc_h[mt][nt][q] = 0.f;
        }
    }

    // ---- final epilogue: out += 0.1*(h3 + b_out + s + b_sh') ----
#pragma unroll
    for (int mt = 0; mt < 2; mt++) {
        int r0 = wm * 32 + mt * 16 + gid, r1 = r0 + 8;
        float bo0 = g_bias12[b * 256 + 128 + r0] + g_bias0[b * 256 + 128 + r0];
        float bo1 = g_bias12[b * 256 + 128 + r1] + g_bias0[b * 256 + 128 + r1];
#pragma unroll
        for (int nt = 0; nt < 4; nt++) {
            int n = wn * 32 + nt * 8 + tig * 2;
            size_t o0 = (((size_t)(b * NF + r0)) << 15) + n0 + n;
            size_t o1 = (((size_t)(b * NF + r1)) << 15) + n0 + n;
            float2 ov0 = *(float2*)(g_out + o0);
            float2 ov1 = *(float2*)(g_out + o1);
            ov0.x += 0.1f * (acc_h[mt][nt][0] + bo0 + acc_s[mt][nt][0]);
            ov0.y += 0.1f * (acc_h[mt][nt][1] + bo0 + acc_s[mt][nt][1]);
            ov1.x += 0.1f * (acc_h[mt][nt][2] + bo1 + acc_s[mt][nt][2]);
            ov1.y += 0.1f * (acc_h[mt][nt][3] + bo1 + acc_s[mt][nt][3]);
            *(float2*)(g_out + o0) = ov0;
            *(float2*)(g_out + o1) = ov1;
        }
    }
}

// ===================== final channel-mean =====================
__global__ void __launch_bounds__(256) mean_kernel(float* __restrict__ dst)
{
    int idx = blockIdx.x * 256 + threadIdx.x;
    int b = idx >> 15;
    int v = idx & (V - 1);
    const float* p = g_out + (((size_t)b * NF) << 15) + v;
    float s = 0.f;
#pragma unroll 8
    for (int c = 0; c < NF; c++) s += p[(size_t)c << 15];
    dst[idx] = s * (1.0f / 128.0f);
}

// ===================== launch =====================
extern "C" void kernel_launch(void* const* d_in, const int* in_sizes, int n_in,
                              void* d_out, int out_size)
{
    const float* lat = (const float*)d_in[0];
    const float* seed = (const float*)d_in[1];
    const float* Wk = (const float*)d_in[2];
    const float* bk = (const float*)d_in[3];
    float* out = (float*)d_out;

    const int CSMEM = 18 * 1024 * 4;  // 73728
    const int FSMEM = 163840;         // 160KB, 1 CTA/SM
    cudaFuncSetAttribute(conv_kernel, cudaFuncAttributeMaxDynamicSharedMemorySize, CSMEM);
    cudaFuncSetAttribute(fused_gemm3_kernel,
                         cudaFuncAttributeMaxDynamicSharedMemorySize, FSMEM);

    hyper_kernel<<<514, 256>>>(lat, Wk, bk);
    seed_norm_kernel<<<128, 256>>>(seed);
    prep_A12_kernel<<<dim3(128, NB), 128>>>();

    for (int it = 0; it < 4; it++) {
        conv_kernel<<<1024, 512, CSMEM>>>();
        prep_A0_kernel<<<dim3(256, NB), 128>>>();
        fused_gemm3_kernel<<<dim3(256, NB), 512, FSMEM>>>();
    }

    mean_kernel<<<512, 256>>>(out);
}

// round 15
// speedup vs baseline: 1.1224x; 1.1224x over previous
#include <cuda_runtime.h>
#include <cuda_bf16.h>
#include <cstdint>

#define V 32768
#define KTOT 131584
#define NB 4
#define NF 128
#define FIN 384

#define OFF_WIN  0
#define OFF_BIN  49152
#define OFF_WMID 49280
#define OFF_BMID 65664
#define OFF_WOUT 65792
#define OFF_BOUT 82176
#define OFF_WSH  82304
#define OFF_BSH  131456

__device__ float g_ks[NB * KTOT];
__device__ float g_out[NB * NF * V];
__device__ __nv_bfloat16 g_yhi[NB * FIN * V];
__device__ __nv_bfloat16 g_ylo[NB * FIN * V];
__device__ __nv_bfloat16 g_A0hi[NB * 256 * FIN];
__device__ __nv_bfloat16 g_A0lo[NB * 256 * FIN];
__device__ __nv_bfloat16 g_A12hi[NB * 2 * NF * NF];
__device__ __nv_bfloat16 g_A12lo[NB * 2 * NF * NF];
__device__ float g_bias0[NB * 256];
__device__ float g_bias12[NB * 2 * NF];
__device__ float g_pstat[NB * FIN * 4];

// ===================== helpers =====================
__device__ __forceinline__ uint32_t smem_u32(const void* p) {
    uint32_t a;
    asm("{ .reg .u64 t; cvta.to.shared.u64 t, %1; cvt.u32.u64 %0, t; }"
        : "=r"(a) : "l"(p));
    return a;
}
__device__ __forceinline__ uint32_t pack_split(float v) {
    __nv_bfloat16 h = __float2bfloat16_rn(v);
    __nv_bfloat16 l = __float2bfloat16_rn(v - __bfloat162float(h));
    return (uint32_t)__bfloat16_as_ushort(h) |
           ((uint32_t)__bfloat16_as_ushort(l) << 16);
}
__device__ __forceinline__ void split2(float a, float b, uint32_t& hp, uint32_t& lp) {
    uint32_t pa = pack_split(a), pb = pack_split(b);
    hp = __byte_perm(pa, pb, 0x5410);
    lp = __byte_perm(pa, pb, 0x7632);
}
// truncation split: hi = top 16 bits, lo = rn(v - hi)
__device__ __forceinline__ void tsplit(float v, uint32_t& h, uint32_t& l) {
    uint32_t u = __float_as_uint(v);
    h = u >> 16;
    l = (uint32_t)__bfloat16_as_ushort(
        __float2bfloat16_rn(v - __uint_as_float(u & 0xFFFF0000u)));
}
__device__ __forceinline__ void ldsm4(uint32_t* r, uint32_t a) {
    asm volatile("ldmatrix.sync.aligned.m8n8.x4.shared.b16 {%0,%1,%2,%3}, [%4];"
                 : "=r"(r[0]), "=r"(r[1]), "=r"(r[2]), "=r"(r[3]) : "r"(a));
}
__device__ __forceinline__ void ldsm4t(uint32_t* r, uint32_t a) {
    asm volatile("ldmatrix.sync.aligned.m8n8.x4.trans.shared.b16 {%0,%1,%2,%3}, [%4];"
                 : "=r"(r[0]), "=r"(r[1]), "=r"(r[2]), "=r"(r[3]) : "r"(a));
}
__device__ __forceinline__ void mma_bf16(float* c, const uint32_t* a,
                                         const uint32_t* bb) {
    asm volatile(
        "mma.sync.aligned.m16n8k16.row.col.f32.bf16.bf16.f32 "
        "{%0,%1,%2,%3}, {%4,%5,%6,%7}, {%8,%9}, {%0,%1,%2,%3};"
        : "+f"(c[0]), "+f"(c[1]), "+f"(c[2]), "+f"(c[3])
        : "r"(a[0]), "r"(a[1]), "r"(a[2]), "r"(a[3]), "r"(bb[0]), "r"(bb[1]));
}
__device__ __forceinline__ void cpa16(uint32_t dst, const void* src) {
    asm volatile("cp.async.cg.shared.global [%0], [%1], 16;" :: "r"(dst), "l"(src));
}
#define CPA_COMMIT() asm volatile("cp.async.commit_group;" ::: "memory")
#define CPA_WAIT0()  asm volatile("cp.async.wait_group 0;" ::: "memory")
#define SWZ(o)   ((o) ^ (((o) >> 3) & 0x70))
#define SWZ64(o) ((o) ^ (((o) >> 3) & 0x30))

// ===================== hypernet =====================
__global__ void __launch_bounds__(256) hyper_kernel(
    const float* __restrict__ lat, const float* __restrict__ Wk,
    const float* __restrict__ bk)
{
    __shared__ float slat[4 * 512];
    for (int i = threadIdx.x; i < 2048; i += 256) slat[i] = lat[i];
    __syncthreads();
    int j = blockIdx.x * 256 + threadIdx.x;
    if (j >= KTOT) return;
    float bv = bk[j];
    float a0 = bv, a1 = bv, a2 = bv, a3 = bv;
    const float* wp = Wk + j;
#pragma unroll 8
    for (int k = 0; k < 512; k++) {
        float w = wp[(size_t)k * KTOT];
        a0 = fmaf(slat[k], w, a0);
        a1 = fmaf(slat[512 + k], w, a1);
        a2 = fmaf(slat[1024 + k], w, a2);
        a3 = fmaf(slat[1536 + k], w, a3);
    }
    g_ks[j] = a0;
    g_ks[KTOT + j] = a1;
    g_ks[2 * KTOT + j] = a2;
    g_ks[3 * KTOT + j] = a3;
}

// ===================== seed instance-norm =====================
__global__ void __launch_bounds__(256) seed_norm_kernel(const float* __restrict__ seed)
{
    int c = blockIdx.x;
    const float* src = seed + (size_t)c * V;
    float s = 0.f, ss = 0.f;
    for (int i = threadIdx.x; i < V; i += 256) {
        float v = src[i];
        s += v;
        ss = fmaf(v, v, ss);
    }
#pragma unroll
    for (int o = 16; o > 0; o >>= 1) {
        s += __shfl_down_sync(0xffffffffu, s, o);
        ss += __shfl_down_sync(0xffffffffu, ss, o);
    }
    __shared__ float red[2][8];
    __shared__ float st[2];
    int warp = threadIdx.x >> 5, lane = threadIdx.x & 31;
    if (lane == 0) { red[0][warp] = s; red[1][warp] = ss; }
    __syncthreads();
    if (threadIdx.x == 0) {
        float S = 0.f, SS = 0.f;
        for (int w = 0; w < 8; w++) { S += red[0][w]; SS += red[1][w]; }
        float mean = S * (1.0f / V);
        float var = SS * (1.0f / V) - mean * mean;
        st[0] = mean;
        st[1] = rsqrtf(var + 1e-5f);
    }
    __syncthreads();
    float mean = st[0], rstd = st[1];
    for (int i = threadIdx.x; i < V; i += 256) {
        float v = (src[i] - mean) * rstd;
        size_t off = ((size_t)c << 15) + i;
        g_out[off] = v;
        g_out[off + ((size_t)128 << 15)] = v;
        g_out[off + ((size_t)256 << 15)] = v;
        g_out[off + ((size_t)384 << 15)] = v;
    }
}

// ===================== sobel conv + partial stats (2 voxels/thread) =========
// Grid 1024: (bc, half). lane groups of 16: g=lane>>4 row select, li=lane&15,
// each thread owns w = 2*li, 2*li+1. float2 smem loads, uint32 plane stores.
__global__ void __launch_bounds__(512) conv_kernel()
{
    extern __shared__ float sx[];
    int bc2 = blockIdx.x;
    int half = bc2 & 1, bc = bc2 >> 1;
    int b = bc >> 7, c = bc & 127;
    int d0 = half * 16;
    const float* src = g_out + ((size_t)bc << 15);

    for (int i = threadIdx.x; i < 18 * 256; i += 512) {
        int si = i >> 8;
        int gd = d0 - 1 + si;
        float4 v = make_float4(0.f, 0.f, 0.f, 0.f);
        if ((unsigned)gd < 32u) v = ((const float4*)(src + gd * 1024))[i & 255];
        ((float4*)sx)[i] = v;
    }
    __syncthreads();

    int warp = threadIdx.x >> 5, lane = threadIdx.x & 31;
    int g = lane >> 4, li = lane & 15;
    size_t fbase = ((size_t)(b * FIN + 3 * c)) << 15;
    __nv_bfloat16* yh = g_yhi + fbase;
    __nv_bfloat16* yl = g_ylo + fbase;

    float s0s = 0.f, s0q = 0.f, s1s = 0.f, s1q = 0.f, s2s = 0.f, s2q = 0.f;

    for (int rp = warp; rp < 256; rp += 16) {
        int row = rp * 2 + g;            // 0..511
        int ld = row >> 5, h = row & 31;
        float2 cv[3][3];
#pragma unroll
        for (int i = 0; i < 3; i++) {
#pragma unroll
            for (int j = 0; j < 3; j++) {
                int hh = h + j - 1;
                cv[i][j] = ((unsigned)hh < 32u)
                               ? ((const float2*)(sx + (ld + i) * 1024 + hh * 32))[li]
                               : make_float2(0.f, 0.f);
            }
        }
        // column sums per w (x = w0 = 2*li, y = w1 = 2*li+1)
        float S0x = (cv[2][0].x + cv[2][1].x + cv[2][2].x) -
                    (cv[0][0].x + cv[0][1].x + cv[0][2].x);
        float S0y = (cv[2][0].y + cv[2][1].y + cv[2][2].y) -
                    (cv[0][0].y + cv[0][1].y + cv[0][2].y);
        float S1x = (cv[0][2].x + cv[1][2].x + cv[2][2].x) -
                    (cv[0][0].x + cv[1][0].x + cv[2][0].x);
        float S1y = (cv[0][2].y + cv[1][2].y + cv[2][2].y) -
                    (cv[0][0].y + cv[1][0].y + cv[2][0].y);
        float S2x = cv[0][0].x + cv[0][1].x + cv[0][2].x + cv[1][0].x + cv[1][1].x +
                    cv[1][2].x + cv[2][0].x + cv[2][1].x + cv[2][2].x;
        float S2y = cv[0][0].y + cv[0][1].y + cv[0][2].y + cv[1][0].y + cv[1][1].y +
                    cv[1][2].y + cv[2][0].y + cv[2][1].y + cv[2][2].y;

        // neighbors across 16-lane groups: left thread's .y, right thread's .x
        float Lp0 = __shfl_up_sync(0xffffffffu, S0y, 1, 16); if (li == 0) Lp0 = 0.f;
        float Lp1 = __shfl_up_sync(0xffffffffu, S1y, 1, 16); if (li == 0) Lp1 = 0.f;
        float Lp2 = __shfl_up_sync(0xffffffffu, S2y, 1, 16); if (li == 0) Lp2 = 0.f;
        float Rn0 = __shfl_down_sync(0xffffffffu, S0x, 1, 16); if (li == 15) Rn0 = 0.f;
        float Rn1 = __shfl_down_sync(0xffffffffu, S1x, 1, 16); if (li == 15) Rn1 = 0.f;
        float Rn2 = __shfl_down_sync(0xffffffffu, S2x, 1, 16); if (li == 15) Rn2 = 0.f;

        float y0a = Lp0 + S0x + S0y;      // d-grad, voxel w0
        float y0b = S0x + S0y + Rn0;      // voxel w1
        float y1a = Lp1 + S1x + S1y;
        float y1b = S1x + S1y + Rn1;
        float y2a = S2y - Lp2;            // w-grad: (w+1) - (w-1)
        float y2b = Rn2 - S2x;

        int voxel = ((d0 + ld) << 10) + (h << 5) + 2 * li;
        uint32_t h0a, l0a, h0b, l0b, h1a, l1a, h1b, l1b, h2a, l2a, h2b, l2b;
        tsplit(y0a, h0a, l0a); tsplit(y0b, h0b, l0b);
        tsplit(y1a, h1a, l1a); tsplit(y1b, h1b, l1b);
        tsplit(y2a, h2a, l2a); tsplit(y2b, h2b, l2b);
        *(uint32_t*)(yh + voxel) = h0a | (h0b << 16);
        *(uint32_t*)(yl + voxel) = l0a | (l0b << 16);
        *(uint32_t*)(yh + V + voxel) = h1a | (h1b << 16);
        *(uint32_t*)(yl + V + voxel) = l1a | (l1b << 16);
        *(uint32_t*)(yh + 2 * V + voxel) = h2a | (h2b << 16);
        *(uint32_t*)(yl + 2 * V + voxel) = l2a | (l2b << 16);

        s0s += y0a + y0b; s0q = fmaf(y0a, y0a, fmaf(y0b, y0b, s0q));
        s1s += y1a + y1b; s1q = fmaf(y1a, y1a, fmaf(y1b, y1b, s1q));
        s2s += y2a + y2b; s2q = fmaf(y2a, y2a, fmaf(y2b, y2b, s2q));
    }

#pragma unroll
    for (int o = 16; o > 0; o >>= 1) {
        s0s += __shfl_down_sync(0xffffffffu, s0s, o);
        s0q += __shfl_down_sync(0xffffffffu, s0q, o);
        s1s += __shfl_down_sync(0xffffffffu, s1s, o);
        s1q += __shfl_down_sync(0xffffffffu, s1q, o);
        s2s += __shfl_down_sync(0xffffffffu, s2s, o);
        s2q += __shfl_down_sync(0xffffffffu, s2q, o);
    }
    __shared__ float rbuf[16][6];
    if (lane == 0) {
        rbuf[warp][0] = s0s; rbuf[warp][1] = s0q;
        rbuf[warp][2] = s1s; rbuf[warp][3] = s1q;
        rbuf[warp][4] = s2s; rbuf[warp][5] = s2q;
    }
    __syncthreads();
    if (threadIdx.x < 3) {
        int a = threadIdx.x;
        float S = 0.f, SQ = 0.f;
        for (int w = 0; w < 16; w++) { S += rbuf[w][2 * a]; SQ += rbuf[w][2 * a + 1]; }
        int f = b * FIN + 3 * c + a;
        g_pstat[f * 4 + half * 2 + 0] = S;
        g_pstat[f * 4 + half * 2 + 1] = SQ;
    }
}

// ===================== weight prep =====================
__global__ void __launch_bounds__(128) prep_A0_kernel()
{
    int ms = blockIdx.x;
    int b = blockIdx.y;
    const float* ksb = g_ks + (size_t)b * KTOT;
    const float* w = (ms < 128) ? ksb + OFF_WIN + (size_t)ms * FIN
                                : ksb + OFF_WSH + (size_t)(ms - 128) * FIN;
    float b0 = (ms < 128) ? ksb[OFF_BIN + ms] : ksb[OFF_BSH + ms - 128];
    const float* pst = g_pstat + (size_t)(b * FIN) * 4;
    __nv_bfloat16* dh = g_A0hi + ((size_t)b * 256 + ms) * FIN;
    __nv_bfloat16* dl = g_A0lo + ((size_t)b * 256 + ms) * FIN;
    float dot = 0.f;
    for (int k = threadIdx.x; k < FIN; k += 128) {
        float sum = pst[k * 4 + 0] + pst[k * 4 + 2];
        float sq = pst[k * 4 + 1] + pst[k * 4 + 3];
        float mn = sum * (1.0f / V);
        float rs = rsqrtf(sq * (1.0f / V) - mn * mn + 1e-5f);
        float a = w[k] * rs;
        __nv_bfloat16 h = __float2bfloat16_rn(a);
        dh[k] = h;
        dl[k] = __float2bfloat16_rn(a - __bfloat162float(h));
        dot = fmaf(a, mn, dot);
    }
#pragma unroll
    for (int o = 16; o > 0; o >>= 1) dot += __shfl_down_sync(0xffffffffu, dot, o);
    __shared__ float rr[4];
    int warp = threadIdx.x >> 5;
    if ((threadIdx.x & 31) == 0) rr[warp] = dot;
    __syncthreads();
    if (threadIdx.x == 0)
        g_bias0[b * 256 + ms] = b0 - (rr[0] + rr[1] + rr[2] + rr[3]);
}

__global__ void __launch_bounds__(128) prep_A12_kernel()
{
    int m = blockIdx.x;
    int b = blockIdx.y;
    const float* ksb = g_ks + (size_t)b * KTOT;
    int k = threadIdx.x;
    float wm = ksb[OFF_WMID + m * 128 + k];
    float wo = ksb[OFF_WOUT + m * 128 + k];
    __nv_bfloat16 hm = __float2bfloat16_rn(wm);
    __nv_bfloat16 ho = __float2bfloat16_rn(wo);
    size_t i0 = ((size_t)b * 2) * 16384 + m * 128 + k;
    size_t i1 = ((size_t)b * 2 + 1) * 16384 + m * 128 + k;
    g_A12hi[i0] = hm;
    g_A12lo[i0] = __float2bfloat16_rn(wm - __bfloat162float(hm));
    g_A12hi[i1] = ho;
    g_A12lo[i1] = __float2bfloat16_rn(wo - __bfloat162float(ho));
    if (k == 0) {
        g_bias12[b * 256 + m] = ksb[OFF_BMID + m];
        g_bias12[b * 256 + 128 + m] = ksb[OFF_BOUT + m];
    }
}

// ===================== fused residual block (R13 winner, unchanged) =========
__global__ void __launch_bounds__(256, 2) fused_gemm2_kernel()
{
    extern __shared__ char smem[];
    uint32_t sb = smem_u32(smem);
    int tid = threadIdx.x, lane = tid & 31, wid = tid >> 5;
    int wm = wid & 3, wn = wid >> 2;
    int b = blockIdx.y;
    int n0 = blockIdx.x * 64;
    int lrow = lane & 15, lcol = (lane >> 4) * 8;
    int gid = lane >> 2, tig = lane & 3;

    const __nv_bfloat16* yh = g_yhi + ((size_t)b * FIN << 15);
    const __nv_bfloat16* yl = g_ylo + ((size_t)b * FIN << 15);
    const __nv_bfloat16* A0h = g_A0hi + (size_t)b * 256 * FIN;
    const __nv_bfloat16* A0l = g_A0lo + (size_t)b * 256 * FIN;
    const __nv_bfloat16* A12h = g_A12hi + (size_t)b * 2 * 16384;
    const __nv_bfloat16* A12l = g_A12lo + (size_t)b * 2 * 16384;

    int yr = tid >> 3, yseg = tid & 7;

    auto issueA0 = [&](int c) {
        uint32_t dh = sb + (c & 1) * 32768, dl = dh + 16384;
        const __nv_bfloat16* sh = A0h + c * 32;
        const __nv_bfloat16* sl = A0l + c * 32;
#pragma unroll
        for (int i = 0; i < 4; i++) {
            int q = tid + i * 256;
            int m = q >> 2, seg = q & 3;
            uint32_t off = SWZ64((uint32_t)(m * 64 + seg * 16));
            cpa16(dh + off, sh + (size_t)m * FIN + seg * 8);
            cpa16(dl + off, sl + (size_t)m * FIN + seg * 8);
        }
        uint32_t yb = sb + 65536 + (c & 1) * 8192;
        uint32_t off = SWZ((uint32_t)(yr * 128 + yseg * 16));
        size_t gof = ((size_t)(c * 32 + yr) << 15) + n0 + yseg * 8;
        cpa16(yb + off, yh + gof);
        cpa16(yb + 4096 + off, yl + gof);
        CPA_COMMIT();
    };

    issueA0(0);

    float acc_h[2][4][4], acc_s[2][4][4];
#pragma unroll
    for (int mt = 0; mt < 2; mt++)
#pragma unroll
        for (int nt = 0; nt < 4; nt++)
#pragma unroll
            for (int q = 0; q < 4; q++) {
                acc_h[mt][nt][q] = 0.f;
                acc_s[mt][nt][q] = 0.f;
            }

    CPA_WAIT0();
    __syncthreads();

    for (int c = 0; c < 12; c++) {
        if (c < 11) issueA0(c + 1);
        uint32_t ab = sb + (c & 1) * 32768;
        uint32_t ybh = sb + 65536 + (c & 1) * 8192, ybl = ybh + 4096;
#pragma unroll
        for (int ks = 0; ks < 2; ks++) {
            int kk = ks * 16;
            uint32_t bh[4][2], bl[4][2];
#pragma unroll
            for (int g = 0; g < 2; g++) {
                uint32_t off = SWZ(
                    (uint32_t)((kk + lrow) * 128 + (wn * 32 + g * 16 + lcol) * 2));
                uint32_t t0[4], t1[4];
                ldsm4t(t0, ybh + off);
                ldsm4t(t1, ybl + off);
                bh[g * 2][0] = t0[0]; bh[g * 2][1] = t0[1];
                bh[g * 2 + 1][0] = t0[2]; bh[g * 2 + 1][1] = t0[3];
                bl[g * 2][0] = t1[0]; bl[g * 2][1] = t1[1];
                bl[g * 2 + 1][0] = t1[2]; bl[g * 2 + 1][1] = t1[3];
            }
            uint32_t ah[2][4], al[2][4];
#pragma unroll
            for (int mt = 0; mt < 2; mt++) {
                uint32_t off = SWZ64(
                    (uint32_t)((wm * 32 + mt * 16 + lrow) * 64 + (kk + lcol) * 2));
                ldsm4(ah[mt], ab + off);
                ldsm4(al[mt], ab + 16384 + off);
            }
#pragma unroll
            for (int mt = 0; mt < 2; mt++)
#pragma unroll
                for (int nt = 0; nt < 4; nt++) {
                    mma_bf16(acc_h[mt][nt], ah[mt], bh[nt]);
                    mma_bf16(acc_h[mt][nt], ah[mt], bl[nt]);
                    mma_bf16(acc_h[mt][nt], al[mt], bh[nt]);
                }
#pragma unroll
            for (int mt = 0; mt < 2; mt++) {
                uint32_t off = SWZ64((uint32_t)(
                    (128 + wm * 32 + mt * 16 + lrow) * 64 + (kk + lcol) * 2));
                ldsm4(ah[mt], ab + off);
                ldsm4(al[mt], ab + 16384 + off);
            }
#pragma unroll
            for (int mt = 0; mt < 2; mt++)
#pragma unroll
                for (int nt = 0; nt < 4; nt++) {
                    mma_bf16(acc_s[mt][nt], ah[mt], bh[nt]);
                    mma_bf16(acc_s[mt][nt], ah[mt], bl[nt]);
                    mma_bf16(acc_s[mt][nt], al[mt], bh[nt]);
                }
        }
        CPA_WAIT0();
        __syncthreads();
    }

    {
        uint32_t dh = sb, dl = sb + 8192;
#pragma unroll
        for (int i = 0; i < 2; i++) {
            int q = tid + i * 256;
            int m = q >> 2, seg = q & 3;
            uint32_t off = SWZ64((uint32_t)(m * 64 + seg * 16));
            cpa16(dh + off, A12h + m * 128 + seg * 8);
            cpa16(dl + off, A12l + m * 128 + seg * 8);
        }
        CPA_COMMIT();
    }
#pragma unroll
    for (int mt = 0; mt < 2; mt++) {
        int r0 = wm * 32 + mt * 16 + gid, r1 = r0 + 8;
        float bi0 = g_bias0[b * 256 + r0], bi1 = g_bias0[b * 256 + r1];
#pragma unroll
        for (int nt = 0; nt < 4; nt++) {
            int n = wn * 32 + nt * 8 + tig * 2;
            uint32_t hp, lp;
            split2(fmaxf(acc_h[mt][nt][0] + bi0, 0.f),
                   fmaxf(acc_h[mt][nt][1] + bi0, 0.f), hp, lp);
            uint32_t off = SWZ((uint32_t)(r0 * 128 + n * 2));
            *(uint32_t*)(smem + 32768 + off) = hp;
            *(uint32_t*)(smem + 49152 + off) = lp;
            split2(fmaxf(acc_h[mt][nt][2] + bi1, 0.f),
                   fmaxf(acc_h[mt][nt][3] + bi1, 0.f), hp, lp);
            off = SWZ((uint32_t)(r1 * 128 + n * 2));
            *(uint32_t*)(smem + 32768 + off) = hp;
            *(uint32_t*)(smem + 49152 + off) = lp;
        }
    }
#pragma unroll
    for (int mt = 0; mt < 2; mt++)
#pragma unroll
        for (int nt = 0; nt < 4; nt++)
#pragma unroll
            for (int q = 0; q < 4; q++) acc_h[mt][nt][q] = 0.f;

    for (int idx = 0; idx < 8; idx++) {
        CPA_WAIT0();
        __syncthreads();
        if (idx < 7) {
            int ns = (idx + 1) >> 2, nc = (idx + 1) & 3;
            const __nv_bfloat16* sh = A12h + (size_t)ns * 16384 + nc * 32;
            const __nv_bfloat16* sl = A12l + (size_t)ns * 16384 + nc * 32;
            uint32_t dh = sb + ((idx + 1) & 1) * 16384, dl = dh + 8192;
#pragma unroll
            for (int i = 0; i < 2; i++) {
                int q = tid + i * 256;
                int m = q >> 2, seg = q & 3;
                uint32_t off = SWZ64((uint32_t)(m * 64 + seg * 16));
                cpa16(dh + off, sh + m * 128 + seg * 8);
                cpa16(dl + off, sl + m * 128 + seg * 8);
            }
            CPA_COMMIT();
        }
        uint32_t ab = sb + (idx & 1) * 16384;
        uint32_t srcH = sb + ((idx < 4) ? 32768 : 65536);
        uint32_t srcL = sb + ((idx < 4) ? 49152 : 81920);
        int krow = (idx & 3) * 32;
#pragma unroll
        for (int ks = 0; ks < 2; ks++) {
            int kk = ks * 16;
            uint32_t bh[4][2], bl[4][2];
#pragma unroll
            for (int g = 0; g < 2; g++) {
                uint32_t off = SWZ((uint32_t)((krow + kk + lrow) * 128 +
                                              (wn * 32 + g * 16 + lcol) * 2));
                uint32_t t0[4], t1[4];
                ldsm4t(t0, srcH + off);
                ldsm4t(t1, srcL + off);
                bh[g * 2][0] = t0[0]; bh[g * 2][1] = t0[1];
                bh[g * 2 + 1][0] = t0[2]; bh[g * 2 + 1][1] = t0[3];
                bl[g * 2][0] = t1[0]; bl[g * 2][1] = t1[1];
                bl[g * 2 + 1][0] = t1[2]; bl[g * 2 + 1][1] = t1[3];
            }
            uint32_t ah[2][4], al[2][4];
#pragma unroll
            for (int mt = 0; mt < 2; mt++) {
                uint32_t off = SWZ64(
                    (uint32_t)((wm * 32 + mt * 16 + lrow) * 64 + (kk + lcol) * 2));
                ldsm4(ah[mt], ab + off);
                ldsm4(al[mt], ab + 8192 + off);
            }
#pragma unroll
            for (int mt = 0; mt < 2; mt++)
#pragma unroll
                for (int nt = 0; nt < 4; nt++) {
                    mma_bf16(acc_h[mt][nt], ah[mt], bh[nt]);
                    mma_bf16(acc_h[mt][nt], ah[mt], bl[nt]);
                    mma_bf16(acc_h[mt][nt], al[mt], bh[nt]);
                }
        }
        if (idx == 3) {
#pragma unroll
            for (int mt = 0; mt < 2; mt++) {
                int r0 = wm * 32 + mt * 16 + gid, r1 = r0 + 8;
                float bi0 = g_bias12[b * 256 + r0], bi1 = g_bias12[b * 256 + r1];
#pragma unroll
                for (int nt = 0; nt < 4; nt++) {
                    int n = wn * 32 + nt * 8 + tig * 2;
                    uint32_t hp, lp;
                    split2(fmaxf(acc_h[mt][nt][0] + bi0, 0.f),
                           fmaxf(acc_h[mt][nt][1] + bi0, 0.f), hp, lp);
                    uint32_t off = SWZ((uint32_t)(r0 * 128 + n * 2));
                    *(uint32_t*)(smem + 65536 + off) = hp;
                    *(uint32_t*)(smem + 81920 + off) = lp;
                    split2(fmaxf(acc_h[mt][nt][2] + bi1, 0.f),
                           fmaxf(acc_h[mt][nt][3] + bi1, 0.f), hp, lp);
                    off = SWZ((uint32_t)(r1 * 128 + n * 2));
                    *(uint32_t*)(smem + 65536 + off) = hp;
                    *(uint32_t*)(smem + 81920 + off) = lp;
                }
            }
#pragma unroll
            for (int mt = 0; mt < 2; mt++)
#pragma unroll
                for (int nt = 0; nt < 4; nt++)
#pragma unroll
                    for (int q = 0; q < 4; q++) acc_h[mt][nt][q] = 0.f;
        }
    }

#pragma unroll
    for (int mt = 0; mt < 2; mt++) {
        int r0 = wm * 32 + mt * 16 + gid, r1 = r0 + 8;
        float bo0 = g_bias12[b * 256 + 128 + r0] + g_bias0[b * 256 + 128 + r0];
        float bo1 = g_bias12[b * 256 + 128 + r1] + g_bias0[b * 256 + 128 + r1];
#pragma unroll
        for (int nt = 0; nt < 4; nt++) {
            int n = wn * 32 + nt * 8 + tig * 2;
            size_t o0 = (((size_t)(b * NF + r0)) << 15) + n0 + n;
            size_t o1 = (((size_t)(b * NF + r1)) << 15) + n0 + n;
            float2 ov0 = *(float2*)(g_out + o0);
            float2 ov1 = *(float2*)(g_out + o1);
            ov0.x += 0.1f * (acc_h[mt][nt][0] + bo0 + acc_s[mt][nt][0]);
            ov0.y += 0.1f * (acc_h[mt][nt][1] + bo0 + acc_s[mt][nt][1]);
            ov1.x += 0.1f * (acc_h[mt][nt][2] + bo1 + acc_s[mt][nt][2]);
            ov1.y += 0.1f * (acc_h[mt][nt][3] + bo1 + acc_s[mt][nt][3]);
            *(float2*)(g_out + o0) = ov0;
            *(float2*)(g_out + o1) = ov1;
        }
    }
}

// ===================== final channel-mean =====================
__global__ void __launch_bounds__(256) mean_kernel(float* __restrict__ dst)
{
    int idx = blockIdx.x * 256 + threadIdx.x;
    int b = idx >> 15;
    int v = idx & (V - 1);
    const float* p = g_out + (((size_t)b * NF) << 15) + v;
    float s = 0.f;
#pragma unroll 8
    for (int c = 0; c < NF; c++) s += p[(size_t)c << 15];
    dst[idx] = s * (1.0f / 128.0f);
}

// ===================== launch =====================
extern "C" void kernel_launch(void* const* d_in, const int* in_sizes, int n_in,
                              void* d_out, int out_size)
{
    const float* lat = (const float*)d_in[0];
    const float* seed = (const float*)d_in[1];
    const float* Wk = (const float*)d_in[2];
    const float* bk = (const float*)d_in[3];
    float* out = (float*)d_out;

    const int CSMEM = 18 * 1024 * 4;  // 73728
    const int FSMEM = 98304;          // 96KB -> 2 CTAs/SM
    cudaFuncSetAttribute(conv_kernel, cudaFuncAttributeMaxDynamicSharedMemorySize, CSMEM);
    cudaFuncSetAttribute(fused_gemm2_kernel,
                         cudaFuncAttributeMaxDynamicSharedMemorySize, FSMEM);

    hyper_kernel<<<514, 256>>>(lat, Wk, bk);
    seed_norm_kernel<<<128, 256>>>(seed);
    prep_A12_kernel<<<dim3(128, NB), 128>>>();

    for (int it = 0; it < 4; it++) {
        conv_kernel<<<1024, 512, CSMEM>>>();
        prep_A0_kernel<<<dim3(256, NB), 128>>>();
        fused_gemm2_kernel<<<dim3(512, NB), 256, FSMEM>>>();
    }

    mean_kernel<<<512, 256>>>(out);
}